// round 10
// baseline (speedup 1.0000x reference)
#include <cuda_runtime.h>
#include <cuda_bf16.h>
#include <cstdint>

#define NF 27
#define FD 128
#define NPAIRS 351
#define OUT_STRIDE (NF*FD + NPAIRS)   // 3807 (odd -> out rows only 4B-aligned)
#define CHUNK 32
#define ROWB 80                        // 64B payload + 16B pad; ldmatrix conflict-free
#define TILEB (32 * ROWB)              // 2560 B per tile

__device__ __forceinline__ uint32_t smem_u32(const void* p) {
    uint32_t a;
    asm("{ .reg .u64 t; cvta.to.shared.u64 t, %1; cvt.u32.u64 %0, t; }" : "=r"(a) : "l"(p));
    return a;
}

#define LDSM4(q, addr) \
    asm volatile("ldmatrix.sync.aligned.m8n8.x4.shared.b16 {%0,%1,%2,%3}, [%4];" \
                 : "=r"((q)[0]), "=r"((q)[1]), "=r"((q)[2]), "=r"((q)[3]) : "r"(addr))

#define MMA(accv, a0, a1, b) \
    asm volatile("mma.sync.aligned.m16n8k8.row.col.f32.bf16.bf16.f32 " \
                 "{%0,%1,%2,%3}, {%4,%5}, {%6}, {%0,%1,%2,%3};" \
                 : "+f"((accv)[0]), "+f"((accv)[1]), "+f"((accv)[2]), "+f"((accv)[3]) \
                 : "r"(a0), "r"(a1), "r"(b))

// Warp-per-batch Gram via mma.sync bf16 (hi/lo 3-pass, fp32 accum).
// Only the 6 m16n8 tiles that touch the upper triangle are computed.
__global__ void __launch_bounds__(128, 8)
fi_kernel(const float* __restrict__ in, float* __restrict__ out)
{
    __shared__ __align__(16) char smem[4 * 2 * TILEB];   // per warp: hi, lo tiles

    const int w    = threadIdx.x >> 5;
    const int lane = threadIdx.x & 31;
    const long b   = (long)blockIdx.x * 4 + w;

    const float* __restrict__ eb = in  + b * (long)(NF * FD);
    float*       __restrict__ ob = out + b * (long)OUT_STRIDE;

    char* hit = smem + w * 2 * TILEB;
    char* lot = hit + TILEB;
    const uint32_t hib = smem_u32(hit);
    const uint32_t lob = smem_u32(lot);

    // zero pad rows 27..31 once (their outputs are never stored, but keep clean)
    for (int idx = lane; idx < (5 * ROWB) / 4; idx += 32) {
        reinterpret_cast<uint32_t*>(hit + 27 * ROWB)[idx] = 0;
        reinterpret_cast<uint32_t*>(lot + 27 * ROWB)[idx] = 0;
    }

    // 6 tiles: t0..t3 = (m0,g0..g3), t4 = (m1,g2), t5 = (m1,g3)
    float acc[6][4];
#pragma unroll
    for (int t = 0; t < 6; t++)
#pragma unroll
        for (int e = 0; e < 4; e++) acc[t][e] = 0.0f;

    const int half = lane >> 4;
    const int ks   = lane & 15;

    for (int kc = 0; kc < FD; kc += CHUNK) {
        // ---- fill: 14 x (LDG.64 + 2x STG.32 copy + hi/lo cvt + 2x STS.32) ----
#pragma unroll
        for (int it = 0; it < 14; it++) {
            const int f = 2 * it + half;
            float2 v = make_float2(0.0f, 0.0f);
            if (f < NF) {
                v = *reinterpret_cast<const float2*>(eb + f * FD + kc + 2 * ks);
                ob[f * FD + kc + 2 * ks]     = v.x;   // 4B-aligned rows: scalar
                ob[f * FD + kc + 2 * ks + 1] = v.y;
            }
            __nv_bfloat16 h0 = __float2bfloat16(v.x);
            __nv_bfloat16 h1 = __float2bfloat16(v.y);
            __nv_bfloat162 hp = __halves2bfloat162(h0, h1);
            __nv_bfloat162 lp = __halves2bfloat162(
                __float2bfloat16(v.x - __bfloat162float(h0)),
                __float2bfloat16(v.y - __bfloat162float(h1)));
            const int fr = (f < 28) ? f : 27;
            *reinterpret_cast<uint32_t*>(hit + fr * ROWB + 4 * ks) =
                *reinterpret_cast<uint32_t*>(&hp);
            *reinterpret_cast<uint32_t*>(lot + fr * ROWB + 4 * ks) =
                *reinterpret_cast<uint32_t*>(&lp);
        }
        __syncwarp();

        // ---- compute: 2 k16 units per chunk, 6 tiles, 3 passes ----
#pragma unroll
        for (int kk = 0; kk < 2; kk++) {
            const uint32_t boff = (uint32_t)((lane & 15) * ROWB + kk * 32
                                             + (lane >> 4) * 16);
            uint32_t qh0[4], qh1[4], ql0[4], ql1[4];
            LDSM4(qh0, hib + boff);                   // rows 0-15  (hi)
            LDSM4(qh1, hib + boff + 16 * ROWB);       // rows 16-31 (hi)
            LDSM4(ql0, lob + boff);                   // rows 0-15  (lo)
            LDSM4(ql1, lob + boff + 16 * ROWB);       // rows 16-31 (lo)

#pragma unroll
            for (int kstep = 0; kstep < 2; kstep++) {
                const int r0 = 2 * kstep, r1 = 2 * kstep + 1;
                // m0 tiles: A = rows 0-15
#pragma unroll
                for (int g = 0; g < 4; g++) {
                    const uint32_t Bh = (g < 2 ? qh0 : qh1)[2 * kstep + (g & 1)];
                    const uint32_t Bl = (g < 2 ? ql0 : ql1)[2 * kstep + (g & 1)];
                    MMA(acc[g], qh0[r0], qh0[r1], Bh);   // hi*hi
                    MMA(acc[g], qh0[r0], qh0[r1], Bl);   // hi*lo
                    MMA(acc[g], ql0[r0], ql0[r1], Bh);   // lo*hi
                }
                // m1 tiles: A = rows 16-31, only g2, g3 (cols 16-31)
#pragma unroll
                for (int g = 2; g < 4; g++) {
                    const uint32_t Bh = qh1[2 * kstep + (g & 1)];
                    const uint32_t Bl = ql1[2 * kstep + (g & 1)];
                    MMA(acc[2 + g], qh1[r0], qh1[r1], Bh);
                    MMA(acc[2 + g], qh1[r0], qh1[r1], Bl);
                    MMA(acc[2 + g], ql1[r0], ql1[r1], Bh);
                }
            }
        }
        __syncwarp();   // tile reused by next chunk's fill
    }

    // ---- epilogue: scatter triu dots into smem stage, coalesced copy-out ----
    float* stage = reinterpret_cast<float*>(hit);
    {
        const int r4 = lane >> 2;
        const int c2 = 2 * (lane & 3);
        // tile t -> (m, g)
        const int tm[6] = {0, 0, 0, 0, 1, 1};
        const int tg[6] = {0, 1, 2, 3, 2, 3};
#pragma unroll
        for (int t = 0; t < 6; t++) {
#pragma unroll
            for (int e = 0; e < 4; e++) {
                const int i = 16 * tm[t] + r4 + ((e >= 2) ? 8 : 0);
                const int j = 8 * tg[t] + c2 + (e & 1);
                if (j > i && j < NF) {
                    stage[(i * (53 - i)) / 2 + (j - i - 1)] = acc[t][e];
                }
            }
        }
    }
    __syncwarp();

    float* oint = ob + NF * FD;
#pragma unroll
    for (int t = 0; t < 11; t++) {
        const int idx = t * 32 + lane;
        if (idx < NPAIRS) oint[idx] = stage[idx];
    }
}

extern "C" void kernel_launch(void* const* d_in, const int* in_sizes, int n_in,
                              void* d_out, int out_size)
{
    const float* in = (const float*)d_in[0];
    float* out = (float*)d_out;
    const int B = in_sizes[0] / (NF * FD);   // 16384
    fi_kernel<<<B / 4, 128>>>(in, out);
}

// round 12
// speedup vs baseline: 1.2071x; 1.2071x over previous
#include <cuda_runtime.h>
#include <cuda_bf16.h>
#include <cstdint>

#define NF 27
#define FD 128
#define NPAIRS 351
#define OUT_STRIDE (NF*FD + NPAIRS)   // 3807 (odd -> out rows only 4B-aligned)
#define ROWB 80                        // 64B payload + 16B pad; ldmatrix conflict-free
#define TILEB (32 * ROWB)              // 2560 B per tile

__device__ __forceinline__ uint32_t smem_u32(const void* p) {
    uint32_t a;
    asm("{ .reg .u64 t; cvta.to.shared.u64 t, %1; cvt.u32.u64 %0, t; }" : "=r"(a) : "l"(p));
    return a;
}

#define LDSM4(q, addr) \
    asm volatile("ldmatrix.sync.aligned.m8n8.x4.shared.b16 {%0,%1,%2,%3}, [%4];" \
                 : "=r"((q)[0]), "=r"((q)[1]), "=r"((q)[2]), "=r"((q)[3]) : "r"(addr))

#define MMA(accv, a0, a1, b) \
    asm volatile("mma.sync.aligned.m16n8k8.row.col.f32.bf16.bf16.f32 " \
                 "{%0,%1,%2,%3}, {%4,%5}, {%6}, {%0,%1,%2,%3};" \
                 : "+f"((accv)[0]), "+f"((accv)[1]), "+f"((accv)[2]), "+f"((accv)[3]) \
                 : "r"(a0), "r"(a1), "r"(b))

// Warp-per-batch Gram via mma.sync bf16 (hi/lo 3-pass, fp32 accum),
// 6-tile upper-triangle cover, register-staged chunk prefetch pipeline.
__global__ void __launch_bounds__(128, 6)
fi_kernel(const float* __restrict__ in, float* __restrict__ out)
{
    __shared__ __align__(16) char smem[4 * 2 * TILEB];   // per warp: hi, lo tiles

    const int w    = threadIdx.x >> 5;
    const int lane = threadIdx.x & 31;
    const long b   = (long)blockIdx.x * 4 + w;

    const float* __restrict__ eb = in  + b * (long)(NF * FD);
    float*       __restrict__ ob = out + b * (long)OUT_STRIDE;

    char* hit = smem + w * 2 * TILEB;
    char* lot = hit + TILEB;
    const uint32_t hib = smem_u32(hit);
    const uint32_t lob = smem_u32(lot);

    // zero pad rows 27..31 once
    for (int idx = lane; idx < (5 * ROWB) / 4; idx += 32) {
        reinterpret_cast<uint32_t*>(hit + 27 * ROWB)[idx] = 0;
        reinterpret_cast<uint32_t*>(lot + 27 * ROWB)[idx] = 0;
    }

    // 6 tiles: t0..t3 = (m0,g0..g3), t4 = (m1,g2), t5 = (m1,g3)
    float acc[6][4];
#pragma unroll
    for (int t = 0; t < 6; t++)
#pragma unroll
        for (int e = 0; e < 4; e++) acc[t][e] = 0.0f;

    const int half = lane >> 4;
    const int ks   = lane & 15;
    const int col  = 2 * ks;              // k-offset within chunk

    // ---- prologue: load chunk 0 into registers ----
    float2 stg[14];
#pragma unroll
    for (int it = 0; it < 14; it++) {
        const int f = 2 * it + half;
        stg[it] = (f < NF)
            ? *reinterpret_cast<const float2*>(eb + f * FD + col)
            : make_float2(0.0f, 0.0f);
    }

#pragma unroll
    for (int c = 0; c < 4; c++) {
        const int kc = c * 32;

        // ---- convert + copy-out + STS (consumes stg of chunk c) ----
#pragma unroll
        for (int it = 0; it < 14; it++) {
            const int f = 2 * it + half;
            const float2 v = stg[it];
            if (f < NF) {
                ob[f * FD + kc + col]     = v.x;   // rows only 4B-aligned: scalar
                ob[f * FD + kc + col + 1] = v.y;
            }
            __nv_bfloat16 h0 = __float2bfloat16(v.x);
            __nv_bfloat16 h1 = __float2bfloat16(v.y);
            __nv_bfloat162 hp = __halves2bfloat162(h0, h1);
            __nv_bfloat162 lp = __halves2bfloat162(
                __float2bfloat16(v.x - __bfloat162float(h0)),
                __float2bfloat16(v.y - __bfloat162float(h1)));
            const int fr = (f < 28) ? f : 27;
            *reinterpret_cast<uint32_t*>(hit + fr * ROWB + 4 * ks) =
                *reinterpret_cast<uint32_t*>(&hp);
            *reinterpret_cast<uint32_t*>(lot + fr * ROWB + 4 * ks) =
                *reinterpret_cast<uint32_t*>(&lp);
        }
        __syncwarp();

        // ---- prefetch chunk c+1 (overlaps the MMA phase below) ----
        if (c < 3) {
            const int kn = kc + 32;
#pragma unroll
            for (int it = 0; it < 14; it++) {
                const int f = 2 * it + half;
                if (f < NF)
                    stg[it] = *reinterpret_cast<const float2*>(eb + f * FD + kn + col);
            }
        }

        // ---- compute chunk c: 2 k16 units, 6 tiles, 3 passes ----
#pragma unroll
        for (int kk = 0; kk < 2; kk++) {
            const uint32_t boff = (uint32_t)((lane & 15) * ROWB + kk * 32
                                             + (lane >> 4) * 16);
            uint32_t qh0[4], qh1[4], ql0[4], ql1[4];
            LDSM4(qh0, hib + boff);                   // rows 0-15  (hi)
            LDSM4(qh1, hib + boff + 16 * ROWB);       // rows 16-31 (hi)
            LDSM4(ql0, lob + boff);                   // rows 0-15  (lo)
            LDSM4(ql1, lob + boff + 16 * ROWB);       // rows 16-31 (lo)

#pragma unroll
            for (int kstep = 0; kstep < 2; kstep++) {
                const int r0 = 2 * kstep, r1 = 2 * kstep + 1;
#pragma unroll
                for (int g = 0; g < 4; g++) {
                    const uint32_t Bh = (g < 2 ? qh0 : qh1)[2 * kstep + (g & 1)];
                    const uint32_t Bl = (g < 2 ? ql0 : ql1)[2 * kstep + (g & 1)];
                    MMA(acc[g], qh0[r0], qh0[r1], Bh);   // hi*hi
                    MMA(acc[g], qh0[r0], qh0[r1], Bl);   // hi*lo
                    MMA(acc[g], ql0[r0], ql0[r1], Bh);   // lo*hi
                }
#pragma unroll
                for (int g = 2; g < 4; g++) {
                    const uint32_t Bh = qh1[2 * kstep + (g & 1)];
                    const uint32_t Bl = ql1[2 * kstep + (g & 1)];
                    MMA(acc[2 + g], qh1[r0], qh1[r1], Bh);
                    MMA(acc[2 + g], qh1[r0], qh1[r1], Bl);
                    MMA(acc[2 + g], ql1[r0], ql1[r1], Bh);
                }
            }
        }
        __syncwarp();   // tiles reused by next iteration's STS
    }

    // ---- epilogue: scatter triu dots into smem stage, coalesced copy-out ----
    float* stage = reinterpret_cast<float*>(hit);
    {
        const int r4 = lane >> 2;
        const int c2 = 2 * (lane & 3);
        const int tm[6] = {0, 0, 0, 0, 1, 1};
        const int tg[6] = {0, 1, 2, 3, 2, 3};
#pragma unroll
        for (int t = 0; t < 6; t++) {
#pragma unroll
            for (int e = 0; e < 4; e++) {
                const int i = 16 * tm[t] + r4 + ((e >= 2) ? 8 : 0);
                const int j = 8 * tg[t] + c2 + (e & 1);
                if (j > i && j < NF) {
                    stage[(i * (53 - i)) / 2 + (j - i - 1)] = acc[t][e];
                }
            }
        }
    }
    __syncwarp();

    float* oint = ob + NF * FD;
#pragma unroll
    for (int t = 0; t < 11; t++) {
        const int idx = t * 32 + lane;
        if (idx < NPAIRS) oint[idx] = stage[idx];
    }
}

extern "C" void kernel_launch(void* const* d_in, const int* in_sizes, int n_in,
                              void* d_out, int out_size)
{
    const float* in = (const float*)d_in[0];
    float* out = (float*)d_out;
    const int B = in_sizes[0] / (NF * FD);   // 16384
    fi_kernel<<<B / 4, 128>>>(in, out);
}

// round 13
// speedup vs baseline: 1.2725x; 1.0542x over previous
#include <cuda_runtime.h>
#include <cuda_bf16.h>
#include <cstdint>

#define NF 27
#define FD 128
#define NPAIRS 351
#define OUT_STRIDE (NF*FD + NPAIRS)   // 3807 (odd -> out rows only 4B-aligned)
#define ROWB 80                        // tile row: 64B payload + 16B pad (ldmatrix clean)
#define TILEB (32 * ROWB)              // 2560 B per bf16 tile
#define FBUFB (NF * 128)               // 3456 B fp32 chunk buffer (27 rows x 128B)
#define WARPB (2 * TILEB + 2 * FBUFB)  // 12032 B per warp
                                       // 4 warps -> 48128 B static smem (< 48KB cap)

__device__ __forceinline__ uint32_t smem_u32(const void* p) {
    uint32_t a;
    asm("{ .reg .u64 t; cvta.to.shared.u64 t, %1; cvt.u32.u64 %0, t; }" : "=r"(a) : "l"(p));
    return a;
}

#define CP_ASYNC16(saddr, gptr) \
    asm volatile("cp.async.cg.shared.global [%0], [%1], 16;" \
                 :: "r"(saddr), "l"(gptr) : "memory")
#define CP_COMMIT()  asm volatile("cp.async.commit_group;" ::: "memory")
#define CP_WAIT(n)   asm volatile("cp.async.wait_group %0;" :: "n"(n) : "memory")

#define LDSM4(q, addr) \
    asm volatile("ldmatrix.sync.aligned.m8n8.x4.shared.b16 {%0,%1,%2,%3}, [%4];" \
                 : "=r"((q)[0]), "=r"((q)[1]), "=r"((q)[2]), "=r"((q)[3]) : "r"(addr))

#define MMA(accv, a0, a1, b) \
    asm volatile("mma.sync.aligned.m16n8k8.row.col.f32.bf16.bf16.f32 " \
                 "{%0,%1,%2,%3}, {%4,%5}, {%6}, {%0,%1,%2,%3};" \
                 : "+f"((accv)[0]), "+f"((accv)[1]), "+f"((accv)[2]), "+f"((accv)[3]) \
                 : "r"(a0), "r"(a1), "r"(b))

// Warp-per-batch Gram via mma.sync bf16 (hi/lo 3-pass, fp32 accum),
// 6-tile upper-triangle cover, cp.async double-buffered chunk pipeline.
__global__ void __launch_bounds__(128, 4)
fi_kernel(const float* __restrict__ in, float* __restrict__ out)
{
    __shared__ __align__(16) char smem[4 * WARPB];

    const int w    = threadIdx.x >> 5;
    const int lane = threadIdx.x & 31;
    const long b   = (long)blockIdx.x * 4 + w;

    const char* __restrict__ ebc =
        reinterpret_cast<const char*>(in) + b * (long)(NF * FD) * 4;
    float* __restrict__ ob = out + b * (long)OUT_STRIDE;

    char* hit = smem + w * WARPB;
    char* lot = hit + TILEB;
    char* fb0 = hit + 2 * TILEB;
    char* fb1 = fb0 + FBUFB;
    const uint32_t hib  = smem_u32(hit);
    const uint32_t lob  = smem_u32(lot);
    const uint32_t fba[2] = { smem_u32(fb0), smem_u32(fb1) };

    // zero tile pad rows 27..31 once (convert never writes them)
    for (int idx = lane; idx < (5 * ROWB) / 4; idx += 32) {
        reinterpret_cast<uint32_t*>(hit + 27 * ROWB)[idx] = 0;
        reinterpret_cast<uint32_t*>(lot + 27 * ROWB)[idx] = 0;
    }

    // 6 tiles: t0..t3 = (m0,g0..g3), t4 = (m1,g2), t5 = (m1,g3)
    float acc[6][4];
#pragma unroll
    for (int t = 0; t < 6; t++)
#pragma unroll
        for (int e = 0; e < 4; e++) acc[t][e] = 0.0f;

    const int half = lane >> 4;
    const int ks   = lane & 15;

    // cp.async issue of one 27x32-float chunk: 216 16B segments
    auto issue_chunk = [&](uint32_t fbuf, int kc) {
#pragma unroll
        for (int it = 0; it < 7; it++) {
            const int idx = it * 32 + lane;          // 0..223
            if (idx < NF * 8) {
                const int f = idx >> 3, seg = idx & 7;
                CP_ASYNC16(fbuf + (uint32_t)idx * 16,
                           ebc + f * 512 + kc * 4 + seg * 16);
            }
        }
        CP_COMMIT();
    };

    // prologue: chunks 0 and 1 in flight
    issue_chunk(fba[0], 0);
    issue_chunk(fba[1], 32);

#pragma unroll
    for (int c = 0; c < 4; c++) {
        const int kc = c * 32;
        if (c < 3) { CP_WAIT(1); } else { CP_WAIT(0); }
        __syncwarp();

        const char* fbc = (c & 1) ? fb1 : fb0;

        // ---- convert + copy-out + STS (reads fp32 chunk from smem) ----
#pragma unroll
        for (int it = 0; it < 14; it++) {
            const int f = 2 * it + half;
            if (f < NF) {
                const float2 v = *reinterpret_cast<const float2*>(
                    fbc + f * 128 + ks * 8);
                ob[f * FD + kc + 2 * ks]     = v.x;   // rows 4B-aligned: scalar
                ob[f * FD + kc + 2 * ks + 1] = v.y;
                __nv_bfloat16 h0 = __float2bfloat16(v.x);
                __nv_bfloat16 h1 = __float2bfloat16(v.y);
                __nv_bfloat162 hp = __halves2bfloat162(h0, h1);
                __nv_bfloat162 lp = __halves2bfloat162(
                    __float2bfloat16(v.x - __bfloat162float(h0)),
                    __float2bfloat16(v.y - __bfloat162float(h1)));
                *reinterpret_cast<uint32_t*>(hit + f * ROWB + 4 * ks) =
                    *reinterpret_cast<uint32_t*>(&hp);
                *reinterpret_cast<uint32_t*>(lot + f * ROWB + 4 * ks) =
                    *reinterpret_cast<uint32_t*>(&lp);
            }
        }
        __syncwarp();   // fbuf fully read + tiles fully written

        // ---- refill this buffer with chunk c+2 (flies under the MMAs) ----
        if (c < 2) issue_chunk(fba[c & 1], kc + 64);

        // ---- compute chunk c: 2 k16 units, 6 tiles, 3 passes ----
#pragma unroll
        for (int kk = 0; kk < 2; kk++) {
            const uint32_t boff = (uint32_t)((lane & 15) * ROWB + kk * 32
                                             + (lane >> 4) * 16);
            uint32_t qh0[4], qh1[4], ql0[4], ql1[4];
            LDSM4(qh0, hib + boff);                   // rows 0-15  (hi)
            LDSM4(qh1, hib + boff + 16 * ROWB);       // rows 16-31 (hi)
            LDSM4(ql0, lob + boff);                   // rows 0-15  (lo)
            LDSM4(ql1, lob + boff + 16 * ROWB);       // rows 16-31 (lo)

#pragma unroll
            for (int kstep = 0; kstep < 2; kstep++) {
                const int r0 = 2 * kstep, r1 = 2 * kstep + 1;
#pragma unroll
                for (int g = 0; g < 4; g++) {
                    const uint32_t Bh = (g < 2 ? qh0 : qh1)[2 * kstep + (g & 1)];
                    const uint32_t Bl = (g < 2 ? ql0 : ql1)[2 * kstep + (g & 1)];
                    MMA(acc[g], qh0[r0], qh0[r1], Bh);   // hi*hi
                    MMA(acc[g], qh0[r0], qh0[r1], Bl);   // hi*lo
                    MMA(acc[g], ql0[r0], ql0[r1], Bh);   // lo*hi
                }
#pragma unroll
                for (int g = 2; g < 4; g++) {
                    const uint32_t Bh = qh1[2 * kstep + (g & 1)];
                    const uint32_t Bl = ql1[2 * kstep + (g & 1)];
                    MMA(acc[2 + g], qh1[r0], qh1[r1], Bh);
                    MMA(acc[2 + g], qh1[r0], qh1[r1], Bl);
                    MMA(acc[2 + g], ql1[r0], ql1[r1], Bh);
                }
            }
        }
        __syncwarp();   // tiles reused by next chunk's convert
    }

    // ---- epilogue: scatter triu dots into smem stage, coalesced copy-out ----
    float* stage = reinterpret_cast<float*>(hit);
    {
        const int r4 = lane >> 2;
        const int c2 = 2 * (lane & 3);
        const int tm[6] = {0, 0, 0, 0, 1, 1};
        const int tg[6] = {0, 1, 2, 3, 2, 3};
#pragma unroll
        for (int t = 0; t < 6; t++) {
#pragma unroll
            for (int e = 0; e < 4; e++) {
                const int i = 16 * tm[t] + r4 + ((e >= 2) ? 8 : 0);
                const int j = 8 * tg[t] + c2 + (e & 1);
                if (j > i && j < NF) {
                    stage[(i * (53 - i)) / 2 + (j - i - 1)] = acc[t][e];
                }
            }
        }
    }
    __syncwarp();

    float* oint = ob + NF * FD;
#pragma unroll
    for (int t = 0; t < 11; t++) {
        const int idx = t * 32 + lane;
        if (idx < NPAIRS) oint[idx] = stage[idx];
    }
}

extern "C" void kernel_launch(void* const* d_in, const int* in_sizes, int n_in,
                              void* d_out, int out_size)
{
    const float* in = (const float*)d_in[0];
    float* out = (float*)d_out;
    const int B = in_sizes[0] / (NF * FD);   // 16384
    fi_kernel<<<B / 4, 128>>>(in, out);
}